// round 13
// baseline (speedup 1.0000x reference)
#include <cuda_runtime.h>
#include <cstdint>

// Yolo_Loss: S=56, B=5, C=20, N=128.
// predicts: [N,S,S,B,25] f32, targets: [N,S,S,25] f32, anchors: [5,2] f32.
// TRAFFIC-REDUCED kernel: the loss uses only the best box's body (21 floats);
// the other 4 boxes contribute only 4 coord floats each to the IoU argmax.
// So: (1) gather coords (5x16B/cell) via LDG -> smem; (2) per-thread argmax;
// (3) cooperative warp gather of the best box's 21 floats (nL~2 per warp-LDG);
// (4) targets via one-shot TMA. DRAM sectors/cell ~414B vs 600B streamed.
// Epilogue: fire-and-forget packed u64 RED + last-CTA spinner (single node,
// no fences -- gpu-scope ordering drains in-flight TMA on sm_103a: R5/R6).

#define S_DIM 56
#define N_IMG 128
#define B_BOX 5
#define C_CLS 20
#define CVEC  25                        // C+5
#define PRED_STRIDE (B_BOX * CVEC)      // 125 floats per cell
#define CELLS (N_IMG * S_DIM * S_DIM)   // 401408
#define CPB   128                       // cells per block == threads
#define GRID  (CELLS / CPB)             // 3136

#define COORDS_F (CPB * B_BOX * 4)      // 2560 floats  [cell][box][4]
#define BODIES_F (CPB * 21)             // 2688 floats  [cell][21], stride 21 (odd)
#define TARGETS_F (CPB * CVEC)          // 3200 floats
#define TBYTES   (TARGETS_F * 4)        // 12800 B (16B-multiple)
#define SMEM_F   (COORDS_F + BODIES_F + TARGETS_F)   // 8448 floats
#define SMEM_BYTES (SMEM_F * 4)         // 33792 B

#define FIX_SCALE 262144.0              // 2^18
#define CNT_SHIFT 44
#define SUM_MASK  ((1ULL << CNT_SHIFT) - 1ULL)

__device__ unsigned long long g_acc = 0ULL;

__device__ __forceinline__ float sigmoid_f(float x) {
    float t;
    asm("tanh.approx.f32 %0, %1;" : "=f"(t) : "f"(x * 0.5f));
    return fmaf(0.5f, t, 0.5f);
}

__device__ __forceinline__ uint32_t smem_u32(const void* p) {
    return (uint32_t)__cvta_generic_to_shared(p);
}

__global__ __launch_bounds__(CPB) void yolo_loss_kernel(
    const float* __restrict__ gp,   // predicts
    const float* __restrict__ gt,   // targets
    const float* __restrict__ ga,   // anchors (10 floats)
    float* __restrict__ out)
{
    extern __shared__ __align__(128) float sm[];
    float* smc = sm;                      // coords  [cell*20 + box*4 + i]
    float* smb = sm + COORDS_F;           // bodies  [cell*21 + j]
    float* smt = sm + COORDS_F + BODIES_F;// targets [cell*25 + j]
    __shared__ __align__(8) unsigned long long mbar;
    __shared__ int   bidx_sm[CPB];
    __shared__ float wsum[CPB / 32];

    const int tid = threadIdx.x;
    const uint32_t mbar_a = smem_u32(&mbar);

    if (tid == 0) {
        asm volatile("mbarrier.init.shared.b64 [%0], 1;" :: "r"(mbar_a) : "memory");
    }
    __syncthreads();

    // ---- TMA: targets tile only (fully used bytes) ----
    if (tid == 0) {
        asm volatile("mbarrier.arrive.expect_tx.shared.b64 _, [%0], %1;"
                     :: "r"(mbar_a), "r"((uint32_t)TBYTES) : "memory");
        const char* gtp = (const char*)(gt + (size_t)blockIdx.x * TARGETS_F);
        asm volatile(
            "cp.async.bulk.shared::cta.global.mbarrier::complete_tx::bytes [%0], [%1], %2, [%3];"
            :: "r"(smem_u32(smt)), "l"(gtp), "r"((uint32_t)TBYTES), "r"(mbar_a) : "memory");
    }

    // ---- Stage 1: gather box coordinates (only 16B of each 100B box) ----
    {
        const float* gpp = gp + (size_t)blockIdx.x * (CPB * PRED_STRIDE);
#pragma unroll
        for (int it = 0; it < COORDS_F / CPB; ++it) {   // 20 iterations
            const int k      = tid + it * CPB;          // 0..2559
            const int box_id = k >> 2;                  // cell*5 + b
            const int i      = k & 3;
            const int cell   = box_id / 5;
            const int b      = box_id - cell * 5;
            smc[k] = __ldg(gpp + cell * PRED_STRIDE + b * CVEC + (C_CLS + 1) + i);
        }
    }

    // ---- Wait for targets TMA; then sync so coords smem is visible ----
    {
        uint32_t done;
        asm volatile(
            "{\n\t.reg .pred p;\n\t"
            "mbarrier.try_wait.parity.acquire.cta.shared::cta.b64 p, [%1], 0;\n\t"
            "selp.b32 %0, 1, 0, p;\n\t}"
            : "=r"(done) : "r"(mbar_a) : "memory");
        if (!done) {
            asm volatile(
                "{\n\t.reg .pred P1;\n\t"
                "WAIT_LOOP_%=:\n\t"
                "mbarrier.try_wait.parity.acquire.cta.shared::cta.b64 P1, [%0], 0, 0x989680;\n\t"
                "@P1 bra.uni WAIT_DONE_%=;\n\t"
                "bra.uni WAIT_LOOP_%=;\n\t"
                "WAIT_DONE_%=:\n\t}"
                :: "r"(mbar_a) : "memory");
        }
    }
    __syncthreads();

    // ---- Stage 2: per-thread IoU argmax from coords (targets in smem) ----
    const float* tc = smt + tid * CVEC;   // stride 25 (odd): conflict-free

    const float e   = tc[C_CLS];
    const float tcx = tc[C_CLS + 1], tcy = tc[C_CLS + 2];
    const float tw  = tc[C_CLS + 3], th  = tc[C_CLS + 4];
    const float tx1 = tcx - 0.5f * tw, ty1 = tcy - 0.5f * th;
    const float tx2 = tcx + 0.5f * tw, ty2 = tcy + 0.5f * th;
    const float area_t = tw * th;

    float bnum = -1.0f, bden = 1.0f;
    int   bidx = 0;
    float bsx = 0.f, bsy = 0.f, bw = 0.f, bh = 0.f;

#pragma unroll
    for (int b = 0; b < B_BOX; ++b) {
        // LDS.128 at stride-20-float rows: exactly 4 crossbar phases, no excess
        const float4 cd = *(const float4*)(smc + tid * (B_BOX * 4) + b * 4);
        const float sx = sigmoid_f(cd.x);
        const float sy = sigmoid_f(cd.y);
        const float w  = __expf(cd.z) * __ldg(ga + 2 * b);
        const float h  = __expf(cd.w) * __ldg(ga + 2 * b + 1);

        const float x1 = sx - 0.5f * w, y1 = sy - 0.5f * h;
        const float x2 = sx + 0.5f * w, y2 = sy + 0.5f * h;
        const float lx = fmaxf(x1, tx1), ly = fmaxf(y1, ty1);
        const float rx = fminf(x2, tx2), ry = fminf(y2, ty2);
        const float wi = fmaxf(rx - lx, 0.0f);
        const float hi = fmaxf(ry - ly, 0.0f);
        const float inter = wi * hi;
        const float den   = fmaf(w, h, area_t) - inter;

        // iou_b > iou_best  <=>  inter*bden > bnum*den  (strict > == first-max)
        if (inter * bden > bnum * den) {
            bidx = b; bnum = inter; bden = den;
            bsx = sx; bsy = sy; bw = w; bh = h;
        }
    }

    bidx_sm[tid] = bidx;
    __syncthreads();

    // ---- Stage 3: cooperative gather of best-box bodies (21 floats/cell) ----
    // Per round, one warp-LDG touches ONE cell's 84B region (nL~2), not 32 lines.
    {
        const int wrp  = tid >> 5;
        const int lane = tid & 31;
        const size_t cta_base = (size_t)blockIdx.x * (CPB * PRED_STRIDE);
#pragma unroll 4
        for (int r = 0; r < 32; ++r) {
            const int c  = (wrp << 5) + r;
            const int bb = bidx_sm[c];                   // LDS broadcast (free)
            if (lane < 21) {
                const float v = __ldg(gp + cta_base + (size_t)c * PRED_STRIDE
                                         + bb * CVEC + lane);
                smb[c * 21 + lane] = v;
            }
        }
    }
    __syncthreads();

    // ---- Stage 4: per-thread losses ----
    const float e2 = e * e;

    const float dx = bsx - tcx, dy = bsy - tcy;
    float loss = e2 * (dx * dx + dy * dy);

    const float pw = (bw > 0.f) ? sqrtf(bw + 1e-6f)
                                : ((bw < 0.f) ? -sqrtf(-bw + 1e-6f) : 0.f);
    const float ph = (bh > 0.f) ? sqrtf(bh + 1e-6f)
                                : ((bh < 0.f) ? -sqrtf(-bh + 1e-6f) : 0.f);
    const float dw = pw - tw, dh = ph - th;
    loss += e2 * (dw * dw + dh * dh);

    const float* pbest = smb + tid * 21;   // stride 21 (odd): conflict-free
    const float fbidx = (float)bidx;
    float cls = 0.0f;
#pragma unroll
    for (int c = 0; c < C_CLS; ++c) {
        float pv = pbest[c];
        if (c == 0) pv *= fbidx;
        const float d = pv - tc[c];
        cls = fmaf(d, d, cls);
    }
    loss += e2 * cls;

    const float dobj   = pbest[C_CLS] - e;
    const float one_me = 1.0f - e;
    loss += (e2 + one_me * one_me) * dobj * dobj;

    // ---- Reduction: warp shuffle -> block ----
#pragma unroll
    for (int o = 16; o; o >>= 1)
        loss += __shfl_xor_sync(0xffffffffu, loss, o);

    if ((tid & 31) == 0) wsum[tid >> 5] = loss;
    __syncthreads();

    if (tid == 0) {
        float s = 0.0f;
#pragma unroll
        for (int i = 0; i < CPB / 32; ++i) s += wsum[i];

        // ONE fire-and-forget u64 RED: count in high bits, fixed-point sum low.
        const unsigned long long fx =
            (unsigned long long)__double2ll_rn((double)s * FIX_SCALE);
        const unsigned long long contrib = fx + (1ULL << CNT_SHIFT);
        asm volatile("red.relaxed.gpu.global.add.u64 [%0], %1;"
                     :: "l"(&g_acc), "l"(contrib) : "memory");

        // CTA GRID-1 (scheduled last) spins until all contributions applied.
        if (blockIdx.x == GRID - 1) {
            unsigned long long cur;
            for (;;) {
                asm volatile("ld.relaxed.gpu.global.u64 %0, [%1];"
                             : "=l"(cur) : "l"(&g_acc) : "memory");
                if ((cur >> CNT_SHIFT) == (unsigned long long)GRID) break;
                __nanosleep(128);
            }
            *out = (float)((double)(cur & SUM_MASK) * (1.0 / FIX_SCALE));
            asm volatile("st.relaxed.gpu.global.u64 [%0], %1;"
                         :: "l"(&g_acc), "l"(0ULL) : "memory");
        }
    }
}

extern "C" void kernel_launch(void* const* d_in, const int* in_sizes, int n_in,
                              void* d_out, int out_size)
{
    const float* p = (const float*)d_in[0];
    const float* t = (const float*)d_in[1];
    const float* a = (const float*)d_in[2];
    float* out = (float*)d_out;

    cudaFuncSetAttribute(yolo_loss_kernel,
                         cudaFuncAttributeMaxDynamicSharedMemorySize, SMEM_BYTES);

    yolo_loss_kernel<<<GRID, CPB, SMEM_BYTES>>>(p, t, a, out);
}

// round 14
// speedup vs baseline: 1.7849x; 1.7849x over previous
#include <cuda_runtime.h>
#include <cstdint>

// Yolo_Loss: S=56, B=5, C=20, N=128.
// predicts: [N,S,S,B,25] f32, targets: [N,S,S,25] f32, anchors: [5,2] f32.
// R3 config (best measured total 41.0us): persistent grid 148, double-buffered
// one-shot TMA tiles of 128 cells, single kernel node. Epilogue swapped for
// the zero-cost packed u64 RED + last-CTA spinner (R11) -- removes R3's 148
// __threadfence (CCTL.IVALL) drains. No gpu-scope fences anywhere.

#define S_DIM 56
#define N_IMG 128
#define B_BOX 5
#define C_CLS 20
#define CVEC  25
#define CELLS (N_IMG * S_DIM * S_DIM)   // 401408
#define TILE_CELLS 128
#define THREADS    128
#define NTILES (CELLS / TILE_CELLS)     // 3136
#define GRID   148                      // 1 CTA per SM, single wave

#define TILE_P (TILE_CELLS * CVEC * B_BOX)  // 16000 floats
#define TILE_T (TILE_CELLS * CVEC)          //  3200 floats
#define TILE_F (TILE_P + TILE_T)            // 19200 floats per buffer
#define TPB    (TILE_P * 4)                 // 64000 B
#define TTB    (TILE_T * 4)                 // 12800 B
#define TILE_BYTES (TPB + TTB)              // 76800 B
#define SMEM_BYTES (2 * TILE_BYTES)         // 153600 B dynamic smem

#define FIX_SCALE 262144.0                  // 2^18
#define CNT_SHIFT 44
#define SUM_MASK  ((1ULL << CNT_SHIFT) - 1ULL)

__device__ unsigned long long g_acc = 0ULL;

__device__ __forceinline__ float sigmoid_f(float x) {
    float t;
    asm("tanh.approx.f32 %0, %1;" : "=f"(t) : "f"(x * 0.5f));
    return fmaf(0.5f, t, 0.5f);
}

__device__ __forceinline__ uint32_t smem_u32(const void* p) {
    return (uint32_t)__cvta_generic_to_shared(p);
}

__device__ __forceinline__ void mbar_wait(uint32_t mbar_a, uint32_t parity) {
    uint32_t done;
    asm volatile(
        "{\n\t.reg .pred p;\n\t"
        "mbarrier.try_wait.parity.acquire.cta.shared::cta.b64 p, [%1], %2;\n\t"
        "selp.b32 %0, 1, 0, p;\n\t}"
        : "=r"(done) : "r"(mbar_a), "r"(parity) : "memory");
    if (!done) {
        asm volatile(
            "{\n\t.reg .pred P1;\n\t"
            "WAIT_LOOP_%=:\n\t"
            "mbarrier.try_wait.parity.acquire.cta.shared::cta.b64 P1, [%0], %1, 0x989680;\n\t"
            "@P1 bra.uni WAIT_DONE_%=;\n\t"
            "bra.uni WAIT_LOOP_%=;\n\t"
            "WAIT_DONE_%=:\n\t}"
            :: "r"(mbar_a), "r"(parity) : "memory");
    }
}

__global__ __launch_bounds__(THREADS) void yolo_loss_kernel(
    const float* __restrict__ gp,
    const float* __restrict__ gt,
    const float* __restrict__ ga,
    float* __restrict__ out)
{
    extern __shared__ __align__(128) float sm[];          // 2 buffers of TILE_F floats
    __shared__ __align__(8) unsigned long long mbar[2];
    __shared__ float wsum[THREADS / 32];

    const int tid = threadIdx.x;
    const int bid = blockIdx.x;
    const uint32_t mb0 = smem_u32(&mbar[0]);
    const uint32_t mb1 = smem_u32(&mbar[1]);

    if (tid == 0) {
        asm volatile("mbarrier.init.shared.b64 [%0], 1;" :: "r"(mb0) : "memory");
        asm volatile("mbarrier.init.shared.b64 [%0], 1;" :: "r"(mb1) : "memory");
    }
    __syncthreads();

    const int nt = (NTILES - bid + GRID - 1) / GRID;      // tiles for this CTA (21 or 22)

    // ---- TMA issue helper (tid 0 only): tile (bid + k*GRID) -> buffer (k&1) ----
    auto issue = [&](int k) {
        const int t = bid + k * GRID;
        const int b = k & 1;
        const uint32_t mba = b ? mb1 : mb0;
        asm volatile("mbarrier.arrive.expect_tx.shared.b64 _, [%0], %1;"
                     :: "r"(mba), "r"((uint32_t)TILE_BYTES) : "memory");
        const char* srcp = (const char*)(gp + (size_t)t * TILE_P);
        const char* srct = (const char*)(gt + (size_t)t * TILE_T);
        const uint32_t dst = smem_u32(sm + b * TILE_F);
        asm volatile(
            "cp.async.bulk.shared::cta.global.mbarrier::complete_tx::bytes [%0], [%1], %2, [%3];"
            :: "r"(dst), "l"(srcp), "r"((uint32_t)TPB), "r"(mba) : "memory");
        asm volatile(
            "cp.async.bulk.shared::cta.global.mbarrier::complete_tx::bytes [%0], [%1], %2, [%3];"
            :: "r"(dst + TPB), "l"(srct), "r"((uint32_t)TTB), "r"(mba) : "memory");
    };

    if (tid == 0) {
        issue(0);
        if (nt > 1) issue(1);
    }

    // anchors: tiny, read once into registers
    float anc[2 * B_BOX];
#pragma unroll
    for (int i = 0; i < 2 * B_BOX; ++i) anc[i] = __ldg(ga + i);

    float loss = 0.0f;
    int ph0 = 0, ph1 = 0;

    for (int k = 0; k < nt; ++k) {
        const int b = k & 1;
        if (b) { mbar_wait(mb1, ph1); ph1 ^= 1; }
        else   { mbar_wait(mb0, ph0); ph0 ^= 1; }

        const float* sp = sm + b * TILE_F;
        const float* st = sp + TILE_P;
        const float* pc = sp + tid * (CVEC * B_BOX);   // stride 125: conflict-free
        const float* tc = st + tid * CVEC;             // stride 25:  conflict-free

        const float e   = tc[C_CLS];
        const float tcx = tc[C_CLS + 1], tcy = tc[C_CLS + 2];
        const float tw  = tc[C_CLS + 3], th  = tc[C_CLS + 4];
        const float tx1 = tcx - 0.5f * tw, ty1 = tcy - 0.5f * th;
        const float tx2 = tcx + 0.5f * tw, ty2 = tcy + 0.5f * th;
        const float area_t = tw * th;

        float bnum = -1.0f, bden = 1.0f;
        int   bidx = 0;
        float bsx = 0.f, bsy = 0.f, bw = 0.f, bh = 0.f;

#pragma unroll
        for (int bb = 0; bb < B_BOX; ++bb) {
            const float* pb = pc + bb * CVEC;
            const float sx = sigmoid_f(pb[C_CLS + 1]);
            const float sy = sigmoid_f(pb[C_CLS + 2]);
            const float w  = __expf(pb[C_CLS + 3]) * anc[2 * bb];
            const float h  = __expf(pb[C_CLS + 4]) * anc[2 * bb + 1];

            const float x1 = sx - 0.5f * w, y1 = sy - 0.5f * h;
            const float x2 = sx + 0.5f * w, y2 = sy + 0.5f * h;
            const float lx = fmaxf(x1, tx1), ly = fmaxf(y1, ty1);
            const float rx = fminf(x2, tx2), ry = fminf(y2, ty2);
            const float wi = fmaxf(rx - lx, 0.0f);
            const float hi = fmaxf(ry - ly, 0.0f);
            const float inter = wi * hi;
            const float den   = fmaf(w, h, area_t) - inter;

            if (inter * bden > bnum * den) {   // strict > == first-max argmax
                bidx = bb; bnum = inter; bden = den;
                bsx = sx; bsy = sy; bw = w; bh = h;
            }
        }

        const float e2 = e * e;

        const float dx = bsx - tcx, dy = bsy - tcy;
        float l = e2 * (dx * dx + dy * dy);

        const float pw = (bw > 0.f) ? sqrtf(bw + 1e-6f)
                                    : ((bw < 0.f) ? -sqrtf(-bw + 1e-6f) : 0.f);
        const float ph = (bh > 0.f) ? sqrtf(bh + 1e-6f)
                                    : ((bh < 0.f) ? -sqrtf(-bh + 1e-6f) : 0.f);
        const float dw = pw - tw, dh = ph - th;
        l += e2 * (dw * dw + dh * dh);

        const float* pbest = pc + bidx * CVEC;
        const float fbidx = (float)bidx;
        float cls = 0.0f;
#pragma unroll
        for (int c = 0; c < C_CLS; ++c) {
            float pv = pbest[c];
            if (c == 0) pv *= fbidx;
            const float d = pv - tc[c];
            cls = fmaf(d, d, cls);
        }
        l += e2 * cls;

        const float dobj   = pbest[C_CLS] - e;
        const float one_me = 1.0f - e;
        l += (e2 + one_me * one_me) * dobj * dobj;

        loss += l;

        __syncthreads();                      // all readers done with buffer b
        if (tid == 0 && k + 2 < nt) issue(k + 2);
    }

    // ---- CTA reduction ----
#pragma unroll
    for (int o = 16; o; o >>= 1)
        loss += __shfl_xor_sync(0xffffffffu, loss, o);
    if ((tid & 31) == 0) wsum[tid >> 5] = loss;
    __syncthreads();

    // ---- Grid completion: fire-and-forget packed RED + last-CTA spinner ----
    if (tid == 0) {
        float s = 0.0f;
#pragma unroll
        for (int i = 0; i < THREADS / 32; ++i) s += wsum[i];

        const unsigned long long fx =
            (unsigned long long)__double2ll_rn((double)s * FIX_SCALE);
        const unsigned long long contrib = fx + (1ULL << CNT_SHIFT);
        asm volatile("red.relaxed.gpu.global.add.u64 [%0], %1;"
                     :: "l"(&g_acc), "l"(contrib) : "memory");

        if (blockIdx.x == GRID - 1) {
            unsigned long long cur;
            for (;;) {
                asm volatile("ld.relaxed.gpu.global.u64 %0, [%1];"
                             : "=l"(cur) : "l"(&g_acc) : "memory");
                if ((cur >> CNT_SHIFT) == (unsigned long long)GRID) break;
                __nanosleep(128);
            }
            *out = (float)((double)(cur & SUM_MASK) * (1.0 / FIX_SCALE));
            asm volatile("st.relaxed.gpu.global.u64 [%0], %1;"
                         :: "l"(&g_acc), "l"(0ULL) : "memory");
        }
    }
}

extern "C" void kernel_launch(void* const* d_in, const int* in_sizes, int n_in,
                              void* d_out, int out_size)
{
    const float* p = (const float*)d_in[0];
    const float* t = (const float*)d_in[1];
    const float* a = (const float*)d_in[2];
    float* out = (float*)d_out;

    cudaFuncSetAttribute(yolo_loss_kernel,
                         cudaFuncAttributeMaxDynamicSharedMemorySize, SMEM_BYTES);

    yolo_loss_kernel<<<GRID, THREADS, SMEM_BYTES>>>(p, t, a, out);
}